// round 2
// baseline (speedup 1.0000x reference)
#include <cuda_runtime.h>
#include <math.h>

#define BB 8
#define DD 64
#define HH 128
#define WW 256

// Scratch (static device globals — no runtime allocation).
// g_xh  : horizontal input,  layout [w][h*B+b][d]          = [256][1024][64]
// g_vbuf: horizontal output / vertical input, [h][w*B+b][c] = [128][2048][128]
// g_vout: vertical output, [h][w*B+b][c]                    = [128][2048][128]
__device__ float g_xh[(size_t)WW * HH * BB * DD];
__device__ float g_vbuf[(size_t)HH * WW * BB * 128];
__device__ float g_vout[(size_t)HH * WW * BB * 128];

__device__ __forceinline__ float sigm(float x) {
    return 1.0f / (1.0f + __expf(-x));
}
__device__ __forceinline__ float tanh_fast(float x) {
    x = fminf(15.0f, fmaxf(-15.0f, x));
    float e = __expf(2.0f * x);
    return (e - 1.0f) / (e + 1.0f);
}

// img[b][d][h][w]  ->  g_xh[w][h*8+b][d]
__global__ void transpose_in_k(const float* __restrict__ img) {
    __shared__ float tile[32][33];
    const int tx = threadIdx.x, ty = threadIdx.y;
    const int b = blockIdx.z & 7, h = blockIdx.z >> 3;
    const int w0 = blockIdx.x * 32, d0 = blockIdx.y * 32;
#pragma unroll
    for (int i = 0; i < 32; i += 8) {
        int d = d0 + ty + i;
        tile[ty + i][tx] = img[(((size_t)b * DD + d) * HH + h) * WW + w0 + tx];
    }
    __syncthreads();
#pragma unroll
    for (int i = 0; i < 32; i += 8) {
        int w = w0 + ty + i;
        g_xh[((size_t)w * (HH * BB) + blockIdx.z) * DD + d0 + tx] = tile[tx][ty + i];
    }
}

// g_vout[h][w*8+b][c]  ->  out[b][c][h][w]
__global__ void transpose_out_k(float* __restrict__ out) {
    __shared__ float tile[32][33];
    const int tx = threadIdx.x, ty = threadIdx.y;
    const int b = blockIdx.z & 7, h = blockIdx.z >> 3;
    const int w0 = blockIdx.x * 32, c0 = blockIdx.y * 32;
#pragma unroll
    for (int i = 0; i < 32; i += 8) {
        int w = w0 + ty + i;
        tile[ty + i][tx] =
            g_vout[(size_t)h * (WW * BB * 128) + ((size_t)w * BB + b) * 128 + c0 + tx];
    }
    __syncthreads();
#pragma unroll
    for (int i = 0; i < 32; i += 8) {
        int c = c0 + ty + i;
        out[(((size_t)b * 128 + c) * HH + h) * WW + w0 + tx] = tile[tx][ty + i];
    }
}

// Persistent-state bidirectional LSTM pass.
//  VERT=false: x = g_xh  [T=256][1024][64],  out = g_vbuf
//  VERT=true : x = g_vbuf[T=128][2048][128], out = g_vout
// One CTA = one direction x NSEQ sequences. Weights [Wih|Whh] (256 x KD fp32)
// + hidden state live in shared; cell state in registers.
// Thread tile: 4 sequences x 1 j x 4 gates -> 16 accumulators.
// Threads: (NSEQ/4) seq-groups * 64 j  = NSEQ*16.
template <bool VERT, int T, int STOT, int IN, int NSEQ, int OT, int SDIV, int OHI>
__global__ void __launch_bounds__(512, 1)
lstm_pass(const float* __restrict__ WihF, const float* __restrict__ WhhF,
          const float* __restrict__ bihF, const float* __restrict__ bhhF,
          const float* __restrict__ WihB, const float* __restrict__ WhhB,
          const float* __restrict__ bihB, const float* __restrict__ bhhB) {
    constexpr int KD = IN + 64;
    constexpr int KDP = KD + 4;             // pad: 2*? -> row delta lane stride 4 banks, conflict-free LDS.128
    constexpr int NT = NSEQ * 16;
    constexpr int LPT = (NSEQ * IN) / (4 * NT);  // float4 x-loads per thread per step

    const float* x = VERT ? g_vbuf : g_xh;
    float* outbuf = VERT ? g_vout : g_vbuf;

    extern __shared__ float sm[];
    float* Wsh = sm;                        // 256 * KDP
    float* insh = sm + 256 * KDP;           // NSEQ * KDP   ([x_t | h_t] per sequence)
    float* bsum = insh + NSEQ * KDP;        // 256

    const int tid = threadIdx.x;
    const int dir = blockIdx.y;
    const int s0 = blockIdx.x * NSEQ;

    const float* Wih = dir ? WihB : WihF;
    const float* Whh = dir ? WhhB : WhhF;
    const float* bih = dir ? bihB : bihF;
    const float* bhh = dir ? bhhB : bhhF;

    for (int i = tid; i < 256 * IN; i += NT)
        Wsh[(i / IN) * KDP + (i % IN)] = Wih[i];
    for (int i = tid; i < 256 * 64; i += NT)
        Wsh[(i / 64) * KDP + IN + (i % 64)] = Whh[i];
    for (int i = tid; i < 256; i += NT)
        bsum[i] = bih[i] + bhh[i];
    for (int i = tid; i < NSEQ * 64; i += NT)
        insh[(i / 64) * KDP + IN + (i % 64)] = 0.0f;    // h_0 = 0

    // load x at first timestep
    {
        int tt0 = dir ? (T - 1) : 0;
        const float4* src = (const float4*)(x + ((size_t)tt0 * STOT + s0) * IN);
#pragma unroll
        for (int i = 0; i < LPT; i++) {
            int p4 = tid + i * NT;
            float4 v = src[p4];
            int p = p4 * 4;
            *(float4*)&insh[(p / IN) * KDP + (p % IN)] = v;
        }
    }
    __syncthreads();

    const int jgrp = tid & 63;   // j in [0,64)
    const int sgrp = tid >> 6;   // sequence group

    float bj[4];
#pragma unroll
    for (int g = 0; g < 4; g++) bj[g] = bsum[g * 64 + jgrp];

    float acc[4][4];             // [ss][gate]
    float creg[4];
#pragma unroll
    for (int ss = 0; ss < 4; ss++) {
        creg[ss] = 0.0f;
#pragma unroll
        for (int g = 0; g < 4; g++) acc[ss][g] = bj[g];
    }

    const float* wp0 = &Wsh[(0 * 64 + jgrp) * KDP];
    const float* wp1 = &Wsh[(1 * 64 + jgrp) * KDP];
    const float* wp2 = &Wsh[(2 * 64 + jgrp) * KDP];
    const float* wp3 = &Wsh[(3 * 64 + jgrp) * KDP];
    const float* ip0 = &insh[(sgrp * 4 + 0) * KDP];
    const float* ip1 = &insh[(sgrp * 4 + 1) * KDP];
    const float* ip2 = &insh[(sgrp * 4 + 2) * KDP];
    const float* ip3 = &insh[(sgrp * 4 + 3) * KDP];

    for (int t = 0; t < T; t++) {
        const int tt = dir ? (T - 1 - t) : t;
        float4 pre[LPT];
        const bool havepre = (t + 1 < T);
        if (havepre) {
            int tn = dir ? (tt - 1) : (tt + 1);
            const float4* src = (const float4*)(x + ((size_t)tn * STOT + s0) * IN);
#pragma unroll
            for (int i = 0; i < LPT; i++) pre[i] = src[tid + i * NT];
        }

        // gates = [x_t | h_t] @ [Wih | Whh]^T  (+ bias already in acc)
#pragma unroll 4
        for (int k = 0; k < KD; k += 4) {
            float4 w0 = *(const float4*)(wp0 + k);
            float4 w1 = *(const float4*)(wp1 + k);
            float4 w2 = *(const float4*)(wp2 + k);
            float4 w3 = *(const float4*)(wp3 + k);
            const float* ips[4] = {ip0, ip1, ip2, ip3};
#pragma unroll
            for (int ss = 0; ss < 4; ss++) {
                float4 xv = *(const float4*)(ips[ss] + k);
                acc[ss][0] = fmaf(xv.x, w0.x, fmaf(xv.y, w0.y, fmaf(xv.z, w0.z, fmaf(xv.w, w0.w, acc[ss][0]))));
                acc[ss][1] = fmaf(xv.x, w1.x, fmaf(xv.y, w1.y, fmaf(xv.z, w1.z, fmaf(xv.w, w1.w, acc[ss][1]))));
                acc[ss][2] = fmaf(xv.x, w2.x, fmaf(xv.y, w2.y, fmaf(xv.z, w2.z, fmaf(xv.w, w2.w, acc[ss][2]))));
                acc[ss][3] = fmaf(xv.x, w3.x, fmaf(xv.y, w3.y, fmaf(xv.z, w3.z, fmaf(xv.w, w3.w, acc[ss][3]))));
            }
        }
        __syncthreads();   // all reads of insh done

#pragma unroll
        for (int ss = 0; ss < 4; ss++) {
            int ls = sgrp * 4 + ss;
            int s = s0 + ls;
            float iv = sigm(acc[ss][0]);
            float fv = sigm(acc[ss][1]);
            float gv = tanh_fast(acc[ss][2]);
            float ov = sigm(acc[ss][3]);
            float c = fv * creg[ss] + iv * gv;
            creg[ss] = c;
            float hv = ov * tanh_fast(c);
            insh[ls * KDP + IN + jgrp] = hv;
            size_t oidx = (size_t)(s / SDIV) * OHI + (size_t)(s % SDIV) * 128 +
                          (size_t)tt * OT + (size_t)dir * 64 + jgrp;
            outbuf[oidx] = hv;
#pragma unroll
            for (int g = 0; g < 4; g++) acc[ss][g] = bj[g];
        }
        if (havepre) {
#pragma unroll
            for (int i = 0; i < LPT; i++) {
                int p = (tid + i * NT) * 4;
                *(float4*)&insh[(p / IN) * KDP + (p % IN)] = pre[i];
            }
        }
        __syncthreads();   // new x_t+1 / h_t+1 visible
    }
}

// Instantiation parameters
//  Horizontal: T=256, STOT=1024, IN=64,  NSEQ=16 -> NT=256, out idx = h*262144 + w*1024 + b*128
//  Vertical:   T=128, STOT=2048, IN=128, NSEQ=32 -> NT=512, out idx = h*262144 + s2*128
using HorizK = void (*)(const float*, const float*, const float*, const float*,
                        const float*, const float*, const float*, const float*);

extern "C" void kernel_launch(void* const* d_in, const int* in_sizes, int n_in,
                              void* d_out, int out_size) {
    const float* img    = (const float*)d_in[0];
    const float* hWihF  = (const float*)d_in[1];
    const float* hWhhF  = (const float*)d_in[2];
    const float* hbihF  = (const float*)d_in[3];
    const float* hbhhF  = (const float*)d_in[4];
    const float* hWihB  = (const float*)d_in[5];
    const float* hWhhB  = (const float*)d_in[6];
    const float* hbihB  = (const float*)d_in[7];
    const float* hbhhB  = (const float*)d_in[8];
    const float* vWihF  = (const float*)d_in[9];
    const float* vWhhF  = (const float*)d_in[10];
    const float* vbihF  = (const float*)d_in[11];
    const float* vbhhF  = (const float*)d_in[12];
    const float* vWihB  = (const float*)d_in[13];
    const float* vWhhB  = (const float*)d_in[14];
    const float* vbihB  = (const float*)d_in[15];
    const float* vbhhB  = (const float*)d_in[16];
    float* out = (float*)d_out;

    auto hK = lstm_pass<false, 256, 1024, 64, 16, 1024, 8, 262144>;
    auto vK = lstm_pass<true, 128, 2048, 128, 32, 262144, (1 << 28), 0>;

    const int smemH = (256 * (64 + 64 + 4) + 16 * (64 + 64 + 4) + 256) * 4;   // 144,640 B
    const int smemV = (256 * (128 + 64 + 4) + 32 * (128 + 64 + 4) + 256) * 4; // 226,816 B
    cudaFuncSetAttribute(hK, cudaFuncAttributeMaxDynamicSharedMemorySize, smemH);
    cudaFuncSetAttribute(vK, cudaFuncAttributeMaxDynamicSharedMemorySize, smemV);

    // 1) img -> g_xh  (coalesced transpose)
    transpose_in_k<<<dim3(WW / 32, DD / 32, HH * BB), dim3(32, 8)>>>(img);

    // 2) horizontal biLSTM: g_xh -> g_vbuf
    hK<<<dim3(1024 / 16, 2), 256, smemH>>>(hWihF, hWhhF, hbihF, hbhhF,
                                           hWihB, hWhhB, hbihB, hbhhB);

    // 3) vertical biLSTM: g_vbuf -> g_vout
    vK<<<dim3(2048 / 32, 2), 512, smemV>>>(vWihF, vWhhF, vbihF, vbhhF,
                                           vWihB, vWhhB, vbihB, vbhhB);

    // 4) g_vout -> out  (coalesced transpose)
    transpose_out_k<<<dim3(WW / 32, 128 / 32, HH * BB), dim3(32, 8)>>>(out);
}